// round 12
// baseline (speedup 1.0000x reference)
#include <cuda_runtime.h>
#include <cuda_fp16.h>
#include <mma.h>
#include <cstdint>

using namespace nvcuda;

#define NTOK 2048
#define DDIM 512
#define HDIM 2048
#define GNUM 4
#define EPG  4
#define ENUM 16
#define GTP_THR 0.9f
#define TP_THR  0.9f
#define SCALE_W 0.5f

// ---------------- scratch ----------------
__device__ float d_tw[NTOK * ENUM];
__device__ int   d_slot[NTOK * ENUM];
__device__ int   d_bucket_tok[ENUM * NTOK];
__device__ float d_bucket_w[ENUM * NTOK];
__device__ int   d_counts[ENUM];
__device__ __half d_h16[(size_t)ENUM * NTOK * HDIM];    // 128 MB
__device__ float d_partial[(size_t)ENUM * NTOK * DDIM]; // 64 MB

// smem sizes (bytes)
#define UP_HALFS_PER_BUF 14848   // Ah 256*40=10240, B1h 32*72=2304, B3h 2304
#define UP_SMEM (2 * UP_HALFS_PER_BUF * 2)      // 59392
#define DN_HALFS_PER_BUF 14592   // Ah 256*40=10240, Bh 32*136=4352
#define DN_SMEM (2 * DN_HALFS_PER_BUF * 2)      // 58368

// ---------------- helpers ----------------
__device__ __forceinline__ void cvthi4(float4 v, __half* hi) {
    ((__half2*)hi)[0] = __floats2half2_rn(v.x, v.y);
    ((__half2*)hi)[1] = __floats2half2_rn(v.z, v.w);
}

// ---------------- routing ----------------
__device__ __forceinline__ void top2norm(const float* logit, float thr, float* w) {
    float m = logit[0];
    #pragma unroll
    for (int i = 1; i < 4; i++) m = fmaxf(m, logit[i]);
    float p[4], s = 0.f;
    #pragma unroll
    for (int i = 0; i < 4; i++) { p[i] = expf(logit[i] - m); s += p[i]; }
    #pragma unroll
    for (int i = 0; i < 4; i++) p[i] /= s;
    int i0 = 0; float b0 = p[0];
    #pragma unroll
    for (int i = 1; i < 4; i++) if (p[i] > b0) { b0 = p[i]; i0 = i; }
    int i1 = -1; float b1 = -1.f;
    #pragma unroll
    for (int i = 0; i < 4; i++) if (i != i0 && p[i] > b1) { b1 = p[i]; i1 = i; }
    bool act1 = (b0 + b1) <= thr;
    float mp1 = act1 ? b1 : 0.f;
    float den = b0 + mp1 + 1e-9f;
    #pragma unroll
    for (int i = 0; i < 4; i++) w[i] = 0.f;
    w[i0] = b0 / den;
    w[i1] = mp1 / den;
}

__global__ __launch_bounds__(256) void routing_kernel(
    const float* __restrict__ x, const float* __restrict__ Wr,
    const float* __restrict__ br, const float* __restrict__ Wg,
    const float* __restrict__ bg)
{
    int wid = threadIdx.x >> 5, lane = threadIdx.x & 31;
    int n = blockIdx.x * 8 + wid;
    const float* xr = x + (size_t)n * DDIM;
    float xv[16];
    #pragma unroll
    for (int i = 0; i < 16; i++) xv[i] = xr[lane + 32 * i];

    float acc[20];
    #pragma unroll
    for (int g = 0; g < 4; g++) {
        float s = 0.f;
        #pragma unroll
        for (int i = 0; i < 16; i++) s += xv[i] * Wr[(lane + 32 * i) * 4 + g];
        acc[g] = s;
    }
    #pragma unroll
    for (int g = 0; g < 4; g++) {
        #pragma unroll
        for (int e = 0; e < 4; e++) {
            float s = 0.f;
            const float* wgp = Wg + (size_t)g * DDIM * EPG + e;
            #pragma unroll
            for (int i = 0; i < 16; i++) s += xv[i] * wgp[(lane + 32 * i) * 4];
            acc[4 + g * 4 + e] = s;
        }
    }
    #pragma unroll
    for (int o = 16; o; o >>= 1) {
        #pragma unroll
        for (int j = 0; j < 20; j++) acc[j] += __shfl_xor_sync(0xffffffffu, acc[j], o);
    }
    if (lane == 0) {
        float gl[4];
        #pragma unroll
        for (int g = 0; g < 4; g++) gl[g] = acc[g] + br[g];
        float wgrp[4];
        top2norm(gl, GTP_THR, wgrp);
        #pragma unroll
        for (int g = 0; g < 4; g++) {
            float el[4];
            #pragma unroll
            for (int e = 0; e < 4; e++) el[e] = acc[4 + g * 4 + e] + bg[g * 4 + e];
            float wexp[4];
            top2norm(el, TP_THR, wexp);
            #pragma unroll
            for (int e = 0; e < 4; e++) {
                d_tw[n * ENUM + g * 4 + e] = wgrp[g] * wexp[e] * SCALE_W;
                d_slot[n * ENUM + g * 4 + e] = -1;
            }
        }
    }
}

// ---------------- bucket build ----------------
__global__ __launch_bounds__(256) void build_buckets() {
    int e = blockIdx.x;
    int t = threadIdx.x;
    __shared__ int sc[256];
    int base = t * 8;
    float wv[8];
    int flags = 0, cnt = 0;
    #pragma unroll
    for (int j = 0; j < 8; j++) {
        float v = d_tw[(base + j) * ENUM + e];
        wv[j] = v;
        if (v > 0.f) { flags |= 1 << j; cnt++; }
    }
    sc[t] = cnt;
    __syncthreads();
    for (int off = 1; off < 256; off <<= 1) {
        int v = sc[t];
        int add = (t >= off) ? sc[t - off] : 0;
        __syncthreads();
        sc[t] = v + add;
        __syncthreads();
    }
    int pos = sc[t] - cnt;
    #pragma unroll
    for (int j = 0; j < 8; j++) {
        if ((flags >> j) & 1) {
            int n = base + j;
            d_bucket_tok[e * NTOK + pos] = n;
            d_bucket_w[e * NTOK + pos] = wv[j];
            d_slot[n * ENUM + e] = pos;
            pos++;
        }
    }
    if (t == 255) d_counts[e] = sc[255];
}

// =============================================================================
// wmma_up: block 256(M) x 64(N) for BOTH u=xW1 and v=xW3. K-chunk 32, 16 chunks.
// 8 warps (4m x 2n), warp tile 64x32 per matrix. Double-buffered dynamic smem,
// register prefetch, one sync per chunk.
// Layout (halfs, per buffer): Ah[256x40]@0  B1h[32x72]@10240  B3h[32x72]@12544
// =============================================================================
__global__ __launch_bounds__(256, 1) void wmma_up(
    const float* __restrict__ x, const float* __restrict__ W1,
    const float* __restrict__ W3)
{
    extern __shared__ __align__(16) __half SMU[];
    int e = blockIdx.z;
    int cnt = d_counts[e];
    if (cnt == 0) return;
    int cntp = (cnt + 127) & ~127;
    int m0 = blockIdx.y * 256;
    if (m0 >= cntp) return;
    int n0 = blockIdx.x * 64;
    int tid = threadIdx.x, lane = tid & 31, wid = tid >> 5;
    const int NK = DDIM / 32;

    int gi = m0 + tid; if (gi > cnt - 1) gi = cnt - 1;
    const float* xrow = x + (size_t)d_bucket_tok[e * NTOK + gi] * DDIM;
    int kB = tid >> 3, cB = (tid & 7) * 8;   // 32 k-rows x 8 col-groups of 8
    const float* w1p = W1 + (size_t)e * DDIM * HDIM + (size_t)kB * HDIM + n0 + cB;
    const float* w3p = W3 + (size_t)e * DDIM * HDIM + (size_t)kB * HDIM + n0 + cB;

    float4 rA[8], rB1[2], rB3[2];
    auto ldreg = [&](int kc) {
        int k0 = kc * 32;
        #pragma unroll
        for (int q = 0; q < 8; q++) rA[q] = *(const float4*)(xrow + k0 + q * 4);
        rB1[0] = *(const float4*)(w1p + (size_t)k0 * HDIM);
        rB1[1] = *(const float4*)(w1p + (size_t)k0 * HDIM + 4);
        rB3[0] = *(const float4*)(w3p + (size_t)k0 * HDIM);
        rB3[1] = *(const float4*)(w3p + (size_t)k0 * HDIM + 4);
    };
    auto sts = [&](int b) {
        __half* Ah = SMU + b * UP_HALFS_PER_BUF;
        #pragma unroll
        for (int q = 0; q < 8; q++) cvthi4(rA[q], Ah + tid * 40 + q * 4);
        __half* B1h = Ah + 10240;
        __half* B3h = Ah + 12544;
        cvthi4(rB1[0], B1h + kB * 72 + cB);
        cvthi4(rB1[1], B1h + kB * 72 + cB + 4);
        cvthi4(rB3[0], B3h + kB * 72 + cB);
        cvthi4(rB3[1], B3h + kB * 72 + cB + 4);
    };

    int wm = wid & 3, wn = wid >> 2;
    wmma::fragment<wmma::accumulator, 16, 16, 16, float> u[4][2], v[4][2];
    #pragma unroll
    for (int i = 0; i < 4; i++)
        #pragma unroll
        for (int j = 0; j < 2; j++) {
            wmma::fill_fragment(u[i][j], 0.0f);
            wmma::fill_fragment(v[i][j], 0.0f);
        }

    ldreg(0);
    for (int kc = 0; kc < NK; kc++) {
        int b = kc & 1;
        sts(b);
        if (kc + 1 < NK) ldreg(kc + 1);
        __syncthreads();
        __half* Ah = SMU + b * UP_HALFS_PER_BUF;
        __half* B1h = Ah + 10240;
        __half* B3h = Ah + 12544;
        #pragma unroll
        for (int ks = 0; ks < 2; ks++) {
            wmma::fragment<wmma::matrix_a, 16, 16, 16, __half, wmma::row_major> fa[4];
            #pragma unroll
            for (int i = 0; i < 4; i++)
                wmma::load_matrix_sync(fa[i], Ah + (wm * 64 + 16 * i) * 40 + ks * 16, 40);
            wmma::fragment<wmma::matrix_b, 16, 16, 16, __half, wmma::row_major> f1[2], f3[2];
            #pragma unroll
            for (int j = 0; j < 2; j++) {
                int bo = ks * 16 * 72 + wn * 32 + 16 * j;
                wmma::load_matrix_sync(f1[j], B1h + bo, 72);
                wmma::load_matrix_sync(f3[j], B3h + bo, 72);
            }
            #pragma unroll
            for (int i = 0; i < 4; i++)
                #pragma unroll
                for (int j = 0; j < 2; j++) {
                    wmma::mma_sync(u[i][j], fa[i], f1[j], u[i][j]);
                    wmma::mma_sync(v[i][j], fa[i], f3[j], v[i][j]);
                }
        }
        // buffer b rewritten at kc+2; separated by sync at kc+1 (program order)
    }
    __syncthreads();

    // epilogue: h = silu(u)*v -> fp16
    float* epi = (float*)SMU + wid * 576;
    int r = lane >> 1, c0 = (lane & 1) * 8;
    #pragma unroll
    for (int i = 0; i < 4; i++)
        #pragma unroll
        for (int j = 0; j < 2; j++) {
            #pragma unroll
            for (int t = 0; t < u[i][j].num_elements; t++) {
                float uu = u[i][j].x[t];
                u[i][j].x[t] = uu / (1.f + __expf(-uu)) * v[i][j].x[t];
            }
            wmma::store_matrix_sync(epi, u[i][j], 36, wmma::mem_row_major);
            __syncwarp();
            int grow = m0 + wm * 64 + 16 * i + r;
            int gcol = n0 + wn * 32 + 16 * j + c0;
            __half2* op = (__half2*)(d_h16 + ((size_t)e * NTOK + grow) * HDIM + gcol);
            #pragma unroll
            for (int q = 0; q < 4; q++)
                op[q] = __floats2half2_rn(epi[r * 36 + c0 + 2 * q],
                                          epi[r * 36 + c0 + 2 * q + 1]);
            __syncwarp();
        }
}

// =============================================================================
// wmma_down: block 256(M) x 128(N). K-chunk 32, 64 chunks.
// 8 warps (4m x 2n), warp tile 64x64. A (h) fp16 raw-copied; B (W2) converted.
// Layout (halfs, per buffer): Ah[256x40]@0  Bh[32x136]@10240
// =============================================================================
__global__ __launch_bounds__(256, 1) void wmma_down(const float* __restrict__ W2)
{
    extern __shared__ __align__(16) __half SMD[];
    int e = blockIdx.z;
    int cnt = d_counts[e];
    if (cnt == 0) return;
    int cntp = (cnt + 127) & ~127;
    int m0 = blockIdx.y * 256;
    if (m0 >= cntp) return;
    int n0 = blockIdx.x * 128;
    int tid = threadIdx.x, lane = tid & 31, wid = tid >> 5;
    const int NK = HDIM / 32;

    const __half* arow = d_h16 + ((size_t)e * NTOK + m0 + tid) * HDIM;
    int kb = tid >> 3, cb = (tid & 7) * 16;     // 32 k-rows x 8 col-groups of 16
    const float* w2p = W2 + (size_t)e * HDIM * DDIM + (size_t)kb * DDIM + n0 + cb;

    uint4 rA[4];
    float4 rB[4];
    auto ldreg = [&](int kc) {
        int k0 = kc * 32;
        #pragma unroll
        for (int q = 0; q < 4; q++) rA[q] = *(const uint4*)(arow + k0 + q * 8);
        #pragma unroll
        for (int q = 0; q < 4; q++) rB[q] = *(const float4*)(w2p + (size_t)k0 * DDIM + q * 4);
    };
    auto sts = [&](int b) {
        __half* Ah = SMD + b * DN_HALFS_PER_BUF;
        #pragma unroll
        for (int q = 0; q < 4; q++)
            *(uint4*)(Ah + tid * 40 + q * 8) = rA[q];
        __half* Bh = Ah + 10240;
        #pragma unroll
        for (int q = 0; q < 4; q++)
            cvthi4(rB[q], Bh + kb * 136 + cb + q * 4);
    };

    int wm = wid & 3, wn = wid >> 2;
    wmma::fragment<wmma::accumulator, 16, 16, 16, float> c[4][4];
    #pragma unroll
    for (int i = 0; i < 4; i++)
        #pragma unroll
        for (int j = 0; j < 4; j++) wmma::fill_fragment(c[i][j], 0.0f);

    ldreg(0);
    for (int kc = 0; kc < NK; kc++) {
        int b = kc & 1;
        sts(b);
        if (kc + 1 < NK) ldreg(kc + 1);
        __syncthreads();
        __half* Ah = SMD + b * DN_HALFS_PER_BUF;
        __half* Bh = Ah + 10240;
        #pragma unroll
        for (int ks = 0; ks < 2; ks++) {
            wmma::fragment<wmma::matrix_a, 16, 16, 16, __half, wmma::row_major> fa[4];
            #pragma unroll
            for (int i = 0; i < 4; i++)
                wmma::load_matrix_sync(fa[i], Ah + (wm * 64 + 16 * i) * 40 + ks * 16, 40);
            wmma::fragment<wmma::matrix_b, 16, 16, 16, __half, wmma::row_major> fb[4];
            #pragma unroll
            for (int j = 0; j < 4; j++)
                wmma::load_matrix_sync(fb[j], Bh + ks * 16 * 136 + wn * 64 + 16 * j, 136);
            #pragma unroll
            for (int i = 0; i < 4; i++)
                #pragma unroll
                for (int j = 0; j < 4; j++)
                    wmma::mma_sync(c[i][j], fa[i], fb[j], c[i][j]);
        }
    }
    __syncthreads();

    float* epi = (float*)SMD + wid * 576;
    int r = lane >> 1, c0 = (lane & 1) * 8;
    #pragma unroll
    for (int i = 0; i < 4; i++)
        #pragma unroll
        for (int j = 0; j < 4; j++) {
            wmma::store_matrix_sync(epi, c[i][j], 36, wmma::mem_row_major);
            __syncwarp();
            int grow = m0 + wm * 64 + 16 * i + r;
            float w = d_bucket_w[e * NTOK + grow];
            int gcol = n0 + wn * 64 + 16 * j + c0;
            float* op = d_partial + ((size_t)e * NTOK + grow) * DDIM + gcol;
            float4 o0 = { epi[r * 36 + c0] * w,     epi[r * 36 + c0 + 1] * w,
                          epi[r * 36 + c0 + 2] * w, epi[r * 36 + c0 + 3] * w };
            float4 o1 = { epi[r * 36 + c0 + 4] * w, epi[r * 36 + c0 + 5] * w,
                          epi[r * 36 + c0 + 6] * w, epi[r * 36 + c0 + 7] * w };
            *(float4*)op = o0;
            *(float4*)(op + 4) = o1;
            __syncwarp();
        }
}

// ---------------- gather ----------------
__global__ __launch_bounds__(128) void gather_out(float* __restrict__ out) {
    int n = blockIdx.x;
    int tid = threadIdx.x;
    float acc[4] = {0.f, 0.f, 0.f, 0.f};
    #pragma unroll
    for (int e = 0; e < ENUM; e++) {
        int s = d_slot[n * ENUM + e];
        if (s >= 0) {
            const float* pp = d_partial + ((size_t)e * NTOK + s) * DDIM;
            #pragma unroll
            for (int q = 0; q < 4; q++) acc[q] += pp[tid + q * 128];
        }
    }
    #pragma unroll
    for (int q = 0; q < 4; q++) out[(size_t)n * DDIM + tid + q * 128] = acc[q];
}

// ---------------- launch ----------------
extern "C" void kernel_launch(void* const* d_in, const int* in_sizes, int n_in,
                              void* d_out, int out_size)
{
    const float* x  = (const float*)d_in[0];
    const float* Wr = (const float*)d_in[1];
    const float* br = (const float*)d_in[2];
    const float* Wg = (const float*)d_in[3];
    const float* bg = (const float*)d_in[4];
    const float* W1 = (const float*)d_in[5];
    const float* W3 = (const float*)d_in[6];
    const float* W2 = (const float*)d_in[7];
    float* out = (float*)d_out;

    // idempotent; called every launch (no static guards)
    cudaFuncSetAttribute(wmma_up,   cudaFuncAttributeMaxDynamicSharedMemorySize, UP_SMEM);
    cudaFuncSetAttribute(wmma_down, cudaFuncAttributeMaxDynamicSharedMemorySize, DN_SMEM);

    routing_kernel<<<NTOK / 8, 256>>>(x, Wr, br, Wg, bg);                       // 1
    build_buckets<<<ENUM, 256>>>();                                              // 2
    wmma_up<<<dim3(HDIM / 64, NTOK / 256, ENUM), 256, UP_SMEM>>>(x, W1, W3);    // 3
    wmma_down<<<dim3(DDIM / 128, NTOK / 256, ENUM), 256, DN_SMEM>>>(W2);        // 4 <- ncu
    gather_out<<<NTOK, 128>>>(out);                                              // 5
}

// round 13
// speedup vs baseline: 1.2362x; 1.2362x over previous
#include <cuda_runtime.h>
#include <cuda_fp16.h>
#include <mma.h>
#include <cstdint>

using namespace nvcuda;

#define NTOK 2048
#define DDIM 512
#define HDIM 2048
#define GNUM 4
#define EPG  4
#define ENUM 16
#define GTP_THR 0.9f
#define TP_THR  0.9f
#define SCALE_W 0.5f

// ---------------- scratch ----------------
__device__ float d_tw[NTOK * ENUM];
__device__ int   d_slot[NTOK * ENUM];
__device__ int   d_bucket_tok[ENUM * NTOK];
__device__ float d_bucket_w[ENUM * NTOK];
__device__ int   d_counts[ENUM];
__device__ __half d_h16[(size_t)ENUM * NTOK * HDIM];    // 128 MB
__device__ float d_partial[(size_t)ENUM * NTOK * DDIM]; // 64 MB

// up smem: per buffer (halfs): Ah 128*40=5120, B1h 32*136=4352, B3h 4352 -> 13824
#define UP_HALFS_PER_BUF 13824
#define UP_SMEM (2 * UP_HALFS_PER_BUF * 2)   // 55296 B

// ---------------- helpers ----------------
__device__ __forceinline__ void cvthi4(float4 v, __half* hi) {
    ((__half2*)hi)[0] = __floats2half2_rn(v.x, v.y);
    ((__half2*)hi)[1] = __floats2half2_rn(v.z, v.w);
}

// ---------------- routing ----------------
__device__ __forceinline__ void top2norm(const float* logit, float thr, float* w) {
    float m = logit[0];
    #pragma unroll
    for (int i = 1; i < 4; i++) m = fmaxf(m, logit[i]);
    float p[4], s = 0.f;
    #pragma unroll
    for (int i = 0; i < 4; i++) { p[i] = expf(logit[i] - m); s += p[i]; }
    #pragma unroll
    for (int i = 0; i < 4; i++) p[i] /= s;
    int i0 = 0; float b0 = p[0];
    #pragma unroll
    for (int i = 1; i < 4; i++) if (p[i] > b0) { b0 = p[i]; i0 = i; }
    int i1 = -1; float b1 = -1.f;
    #pragma unroll
    for (int i = 0; i < 4; i++) if (i != i0 && p[i] > b1) { b1 = p[i]; i1 = i; }
    bool act1 = (b0 + b1) <= thr;
    float mp1 = act1 ? b1 : 0.f;
    float den = b0 + mp1 + 1e-9f;
    #pragma unroll
    for (int i = 0; i < 4; i++) w[i] = 0.f;
    w[i0] = b0 / den;
    w[i1] = mp1 / den;
}

__global__ __launch_bounds__(256) void routing_kernel(
    const float* __restrict__ x, const float* __restrict__ Wr,
    const float* __restrict__ br, const float* __restrict__ Wg,
    const float* __restrict__ bg)
{
    int wid = threadIdx.x >> 5, lane = threadIdx.x & 31;
    int n = blockIdx.x * 8 + wid;
    const float* xr = x + (size_t)n * DDIM;
    float xv[16];
    #pragma unroll
    for (int i = 0; i < 16; i++) xv[i] = xr[lane + 32 * i];

    float acc[20];
    #pragma unroll
    for (int g = 0; g < 4; g++) {
        float s = 0.f;
        #pragma unroll
        for (int i = 0; i < 16; i++) s += xv[i] * Wr[(lane + 32 * i) * 4 + g];
        acc[g] = s;
    }
    #pragma unroll
    for (int g = 0; g < 4; g++) {
        #pragma unroll
        for (int e = 0; e < 4; e++) {
            float s = 0.f;
            const float* wgp = Wg + (size_t)g * DDIM * EPG + e;
            #pragma unroll
            for (int i = 0; i < 16; i++) s += xv[i] * wgp[(lane + 32 * i) * 4];
            acc[4 + g * 4 + e] = s;
        }
    }
    #pragma unroll
    for (int o = 16; o; o >>= 1) {
        #pragma unroll
        for (int j = 0; j < 20; j++) acc[j] += __shfl_xor_sync(0xffffffffu, acc[j], o);
    }
    if (lane == 0) {
        float gl[4];
        #pragma unroll
        for (int g = 0; g < 4; g++) gl[g] = acc[g] + br[g];
        float wgrp[4];
        top2norm(gl, GTP_THR, wgrp);
        #pragma unroll
        for (int g = 0; g < 4; g++) {
            float el[4];
            #pragma unroll
            for (int e = 0; e < 4; e++) el[e] = acc[4 + g * 4 + e] + bg[g * 4 + e];
            float wexp[4];
            top2norm(el, TP_THR, wexp);
            #pragma unroll
            for (int e = 0; e < 4; e++) {
                d_tw[n * ENUM + g * 4 + e] = wgrp[g] * wexp[e] * SCALE_W;
                d_slot[n * ENUM + g * 4 + e] = -1;
            }
        }
    }
}

// ---------------- bucket build ----------------
__global__ __launch_bounds__(256) void build_buckets() {
    int e = blockIdx.x;
    int t = threadIdx.x;
    __shared__ int sc[256];
    int base = t * 8;
    float wv[8];
    int flags = 0, cnt = 0;
    #pragma unroll
    for (int j = 0; j < 8; j++) {
        float v = d_tw[(base + j) * ENUM + e];
        wv[j] = v;
        if (v > 0.f) { flags |= 1 << j; cnt++; }
    }
    sc[t] = cnt;
    __syncthreads();
    for (int off = 1; off < 256; off <<= 1) {
        int v = sc[t];
        int add = (t >= off) ? sc[t - off] : 0;
        __syncthreads();
        sc[t] = v + add;
        __syncthreads();
    }
    int pos = sc[t] - cnt;
    #pragma unroll
    for (int j = 0; j < 8; j++) {
        if ((flags >> j) & 1) {
            int n = base + j;
            d_bucket_tok[e * NTOK + pos] = n;
            d_bucket_w[e * NTOK + pos] = wv[j];
            d_slot[n * ENUM + e] = pos;
            pos++;
        }
    }
    if (t == 255) d_counts[e] = sc[255];
}

// =============================================================================
// wmma_up: block 128(M) x 128(N) for BOTH u=xW1 and v=xW3. K-chunk 32, 16 chunks.
// 8 warps (2m x 4n), warp tile 64x32 per output matrix: 8 frag loads / 16 MMAs.
// Double-buffered dynamic smem, register prefetch, one sync per chunk.
// Layout per buffer (halfs): Ah[128x40]@0  B1h[32x136]@5120  B3h[32x136]@9472
// =============================================================================
__global__ __launch_bounds__(256, 1) void wmma_up(
    const float* __restrict__ x, const float* __restrict__ W1,
    const float* __restrict__ W3)
{
    extern __shared__ __align__(16) __half SMU[];
    int e = blockIdx.z;
    int cnt = d_counts[e];
    if (cnt == 0) return;
    int cntp = (cnt + 127) & ~127;
    int m0 = blockIdx.y * 128;
    if (m0 >= cntp) return;
    int n0 = blockIdx.x * 128;
    int tid = threadIdx.x, lane = tid & 31, wid = tid >> 5;
    const int NK = DDIM / 32;

    // staging mappings
    int ar = tid >> 1, ap = (tid & 1) * 16;           // A: 128 rows x 32 halfs
    int gi = m0 + ar; if (gi > cnt - 1) gi = cnt - 1;
    const float* xrow = x + (size_t)d_bucket_tok[e * NTOK + gi] * DDIM;
    int kB = tid >> 3, cB = (tid & 7) * 16;           // B: 32 k-rows x 8 col-grps of 16
    const float* w1p = W1 + (size_t)e * DDIM * HDIM + (size_t)kB * HDIM + n0 + cB;
    const float* w3p = W3 + (size_t)e * DDIM * HDIM + (size_t)kB * HDIM + n0 + cB;

    float4 rA[4], rB1[4], rB3[4];
    auto ldreg = [&](int kc) {
        int k0 = kc * 32;
        #pragma unroll
        for (int q = 0; q < 4; q++) rA[q] = *(const float4*)(xrow + k0 + ap + q * 4);
        #pragma unroll
        for (int q = 0; q < 4; q++) {
            rB1[q] = *(const float4*)(w1p + (size_t)k0 * HDIM + q * 4);
            rB3[q] = *(const float4*)(w3p + (size_t)k0 * HDIM + q * 4);
        }
    };
    auto sts = [&](int b) {
        __half* Ah = SMU + b * UP_HALFS_PER_BUF;
        #pragma unroll
        for (int q = 0; q < 4; q++) cvthi4(rA[q], Ah + ar * 40 + ap + q * 4);
        __half* B1h = Ah + 5120;
        __half* B3h = Ah + 9472;
        #pragma unroll
        for (int q = 0; q < 4; q++) {
            cvthi4(rB1[q], B1h + kB * 136 + cB + q * 4);
            cvthi4(rB3[q], B3h + kB * 136 + cB + q * 4);
        }
    };

    int wm = wid & 1, wn = wid >> 1;
    wmma::fragment<wmma::accumulator, 16, 16, 16, float> u[4][2], v[4][2];
    #pragma unroll
    for (int i = 0; i < 4; i++)
        #pragma unroll
        for (int j = 0; j < 2; j++) {
            wmma::fill_fragment(u[i][j], 0.0f);
            wmma::fill_fragment(v[i][j], 0.0f);
        }

    ldreg(0);
    for (int kc = 0; kc < NK; kc++) {
        int b = kc & 1;
        sts(b);
        if (kc + 1 < NK) ldreg(kc + 1);
        __syncthreads();
        __half* Ah = SMU + b * UP_HALFS_PER_BUF;
        __half* B1h = Ah + 5120;
        __half* B3h = Ah + 9472;
        #pragma unroll
        for (int ks = 0; ks < 2; ks++) {
            wmma::fragment<wmma::matrix_a, 16, 16, 16, __half, wmma::row_major> fa[4];
            #pragma unroll
            for (int i = 0; i < 4; i++)
                wmma::load_matrix_sync(fa[i], Ah + (wm * 64 + 16 * i) * 40 + ks * 16, 40);
            wmma::fragment<wmma::matrix_b, 16, 16, 16, __half, wmma::row_major> f1[2], f3[2];
            #pragma unroll
            for (int j = 0; j < 2; j++) {
                int bo = ks * 16 * 136 + wn * 32 + 16 * j;
                wmma::load_matrix_sync(f1[j], B1h + bo, 136);
                wmma::load_matrix_sync(f3[j], B3h + bo, 136);
            }
            #pragma unroll
            for (int i = 0; i < 4; i++)
                #pragma unroll
                for (int j = 0; j < 2; j++) {
                    wmma::mma_sync(u[i][j], fa[i], f1[j], u[i][j]);
                    wmma::mma_sync(v[i][j], fa[i], f3[j], v[i][j]);
                }
        }
        // buffer b rewritten at kc+2; every warp passed sync at kc+1 after its
        // kc MMAs (program order), so no WAR hazard.
    }
    __syncthreads();

    // epilogue: h = silu(u)*v -> fp16 (single rounding; matches prior numerics)
    float* epi = (float*)SMU + wid * 576;
    int r = lane >> 1, c0 = (lane & 1) * 8;
    #pragma unroll
    for (int i = 0; i < 4; i++)
        #pragma unroll
        for (int j = 0; j < 2; j++) {
            #pragma unroll
            for (int t = 0; t < u[i][j].num_elements; t++) {
                float uu = u[i][j].x[t];
                u[i][j].x[t] = uu / (1.f + __expf(-uu)) * v[i][j].x[t];
            }
            wmma::store_matrix_sync(epi, u[i][j], 36, wmma::mem_row_major);
            __syncwarp();
            int grow = m0 + wm * 64 + 16 * i + r;
            int gcol = n0 + wn * 32 + 16 * j + c0;
            __half2* op = (__half2*)(d_h16 + ((size_t)e * NTOK + grow) * HDIM + gcol);
            #pragma unroll
            for (int q = 0; q < 4; q++)
                op[q] = __floats2half2_rn(epi[r * 36 + c0 + 2 * q],
                                          epi[r * 36 + c0 + 2 * q + 1]);
            __syncwarp();
        }
}

// =============================================================================
// wmma_down: block 128(M) x 128(N). K-chunk 32, 64 chunks. (measured-best cfg)
// 8 warps (4m x 2n), warp tile 32x64. A (h) fp16 raw-copied; B (W2) converted.
// Static smem per buffer (halfs): Ah[128x40]@0  Bh[32x136]@5120  (9472)
// =============================================================================
__global__ __launch_bounds__(256, 1) void wmma_down(const float* __restrict__ W2)
{
    __shared__ __align__(16) __half SM[2][9472];   // 37888 B
    int e = blockIdx.z;
    int cnt = d_counts[e];
    if (cnt == 0) return;
    int cntp = (cnt + 127) & ~127;
    int m0 = blockIdx.y * 128;
    if (m0 >= cntp) return;
    int n0 = blockIdx.x * 128;
    int tid = threadIdx.x, lane = tid & 31, wid = tid >> 5;
    const int NK = HDIM / 32;

    int ar = tid >> 1, ap = (tid & 1) * 16;
    const __half* arow = d_h16 + ((size_t)e * NTOK + m0 + ar) * HDIM;
    int kB = tid >> 3, cB = (tid & 7) * 16;
    const float* w2p = W2 + (size_t)e * HDIM * DDIM + (size_t)kB * DDIM + n0 + cB;

    uint4 rA[2];
    float4 rB[4];
    auto ldreg = [&](int kc) {
        int k0 = kc * 32;
        rA[0] = *(const uint4*)(arow + k0 + ap);
        rA[1] = *(const uint4*)(arow + k0 + ap + 8);
        #pragma unroll
        for (int q = 0; q < 4; q++)
            rB[q] = *(const float4*)(w2p + (size_t)k0 * DDIM + q * 4);
    };
    auto sts = [&](int b) {
        __half* Ah = SM[b];
        *(uint4*)(Ah + ar * 40 + ap) = rA[0];
        *(uint4*)(Ah + ar * 40 + ap + 8) = rA[1];
        __half* Bh = SM[b] + 5120;
        #pragma unroll
        for (int q = 0; q < 4; q++)
            cvthi4(rB[q], Bh + kB * 136 + cB + q * 4);
    };

    int wm = wid & 3, wn = wid >> 2;
    wmma::fragment<wmma::accumulator, 16, 16, 16, float> c[2][4];
    #pragma unroll
    for (int i = 0; i < 2; i++)
        #pragma unroll
        for (int j = 0; j < 4; j++) wmma::fill_fragment(c[i][j], 0.0f);

    ldreg(0);
    for (int kc = 0; kc < NK; kc++) {
        int b = kc & 1;
        sts(b);
        if (kc + 1 < NK) ldreg(kc + 1);
        __syncthreads();
        __half* Ah = SM[b];
        __half* Bh = SM[b] + 5120;
        #pragma unroll
        for (int ks = 0; ks < 2; ks++) {
            wmma::fragment<wmma::matrix_a, 16, 16, 16, __half, wmma::row_major> fa[2];
            #pragma unroll
            for (int i = 0; i < 2; i++)
                wmma::load_matrix_sync(fa[i], Ah + (wm * 32 + 16 * i) * 40 + ks * 16, 40);
            wmma::fragment<wmma::matrix_b, 16, 16, 16, __half, wmma::row_major> fb[4];
            #pragma unroll
            for (int j = 0; j < 4; j++)
                wmma::load_matrix_sync(fb[j], Bh + ks * 16 * 136 + wn * 64 + 16 * j, 136);
            #pragma unroll
            for (int i = 0; i < 2; i++)
                #pragma unroll
                for (int j = 0; j < 4; j++)
                    wmma::mma_sync(c[i][j], fa[i], fb[j], c[i][j]);
        }
    }
    __syncthreads();

    float* epi = (float*)SM + wid * 576;
    int r = lane >> 1, c0 = (lane & 1) * 8;
    #pragma unroll
    for (int i = 0; i < 2; i++)
        #pragma unroll
        for (int j = 0; j < 4; j++) {
            wmma::store_matrix_sync(epi, c[i][j], 36, wmma::mem_row_major);
            __syncwarp();
            int grow = m0 + wm * 32 + 16 * i + r;
            float w = d_bucket_w[e * NTOK + grow];
            int gcol = n0 + wn * 64 + 16 * j + c0;
            float* op = d_partial + ((size_t)e * NTOK + grow) * DDIM + gcol;
            float4 o0 = { epi[r * 36 + c0] * w,     epi[r * 36 + c0 + 1] * w,
                          epi[r * 36 + c0 + 2] * w, epi[r * 36 + c0 + 3] * w };
            float4 o1 = { epi[r * 36 + c0 + 4] * w, epi[r * 36 + c0 + 5] * w,
                          epi[r * 36 + c0 + 6] * w, epi[r * 36 + c0 + 7] * w };
            *(float4*)op = o0;
            *(float4*)(op + 4) = o1;
            __syncwarp();
        }
}

// ---------------- gather ----------------
__global__ __launch_bounds__(128) void gather_out(float* __restrict__ out) {
    int n = blockIdx.x;
    int tid = threadIdx.x;
    float acc[4] = {0.f, 0.f, 0.f, 0.f};
    #pragma unroll
    for (int e = 0; e < ENUM; e++) {
        int s = d_slot[n * ENUM + e];
        if (s >= 0) {
            const float* pp = d_partial + ((size_t)e * NTOK + s) * DDIM;
            #pragma unroll
            for (int q = 0; q < 4; q++) acc[q] += pp[tid + q * 128];
        }
    }
    #pragma unroll
    for (int q = 0; q < 4; q++) out[(size_t)n * DDIM + tid + q * 128] = acc[q];
}

// ---------------- launch ----------------
extern "C" void kernel_launch(void* const* d_in, const int* in_sizes, int n_in,
                              void* d_out, int out_size)
{
    const float* x  = (const float*)d_in[0];
    const float* Wr = (const float*)d_in[1];
    const float* br = (const float*)d_in[2];
    const float* Wg = (const float*)d_in[3];
    const float* bg = (const float*)d_in[4];
    const float* W1 = (const float*)d_in[5];
    const float* W3 = (const float*)d_in[6];
    const float* W2 = (const float*)d_in[7];
    float* out = (float*)d_out;

    cudaFuncSetAttribute(wmma_up, cudaFuncAttributeMaxDynamicSharedMemorySize, UP_SMEM);

    routing_kernel<<<NTOK / 8, 256>>>(x, Wr, br, Wg, bg);                        // 1
    build_buckets<<<ENUM, 256>>>();                                               // 2
    wmma_up<<<dim3(HDIM / 128, NTOK / 128, ENUM), 256, UP_SMEM>>>(x, W1, W3);    // 3
    wmma_down<<<dim3(DDIM / 128, NTOK / 128, ENUM), 256>>>(W2);                  // 4 <- ncu
    gather_out<<<NTOK, 128>>>(out);                                               // 5
}

// round 14
// speedup vs baseline: 1.3273x; 1.0737x over previous
#include <cuda_runtime.h>
#include <cuda_fp16.h>
#include <mma.h>
#include <cstdint>

using namespace nvcuda;

#define NTOK 2048
#define DDIM 512
#define HDIM 2048
#define GNUM 4
#define EPG  4
#define ENUM 16
#define GTP_THR 0.9f
#define TP_THR  0.9f
#define SCALE_W 0.5f

// ---------------- scratch ----------------
__device__ float d_tw[NTOK * ENUM];
__device__ int   d_slot[NTOK * ENUM];
__device__ int   d_bucket_tok[ENUM * NTOK];
__device__ float d_bucket_w[ENUM * NTOK];
__device__ int   d_counts[ENUM];
__device__ __half d_h16[(size_t)ENUM * NTOK * HDIM];    // 128 MB
__device__ float d_partial[(size_t)ENUM * NTOK * DDIM]; // 64 MB

// up smem: per buffer (halfs): Ah 128*40=5120, B1h 32*136=4352, B3h 4352 -> 13824
#define UP_HALFS_PER_BUF 13824
#define UP_SMEM (2 * UP_HALFS_PER_BUF * 2)   // 55296 B

// ---------------- helpers ----------------
__device__ __forceinline__ void cvthi4(float4 v, __half* hi) {
    ((__half2*)hi)[0] = __floats2half2_rn(v.x, v.y);
    ((__half2*)hi)[1] = __floats2half2_rn(v.z, v.w);
}

// ---------------- routing ----------------
__device__ __forceinline__ void top2norm(const float* logit, float thr, float* w) {
    float m = logit[0];
    #pragma unroll
    for (int i = 1; i < 4; i++) m = fmaxf(m, logit[i]);
    float p[4], s = 0.f;
    #pragma unroll
    for (int i = 0; i < 4; i++) { p[i] = expf(logit[i] - m); s += p[i]; }
    #pragma unroll
    for (int i = 0; i < 4; i++) p[i] /= s;
    int i0 = 0; float b0 = p[0];
    #pragma unroll
    for (int i = 1; i < 4; i++) if (p[i] > b0) { b0 = p[i]; i0 = i; }
    int i1 = -1; float b1 = -1.f;
    #pragma unroll
    for (int i = 0; i < 4; i++) if (i != i0 && p[i] > b1) { b1 = p[i]; i1 = i; }
    bool act1 = (b0 + b1) <= thr;
    float mp1 = act1 ? b1 : 0.f;
    float den = b0 + mp1 + 1e-9f;
    #pragma unroll
    for (int i = 0; i < 4; i++) w[i] = 0.f;
    w[i0] = b0 / den;
    w[i1] = mp1 / den;
}

__global__ __launch_bounds__(256) void routing_kernel(
    const float* __restrict__ x, const float* __restrict__ Wr,
    const float* __restrict__ br, const float* __restrict__ Wg,
    const float* __restrict__ bg)
{
    int wid = threadIdx.x >> 5, lane = threadIdx.x & 31;
    int n = blockIdx.x * 8 + wid;
    const float* xr = x + (size_t)n * DDIM;
    float xv[16];
    #pragma unroll
    for (int i = 0; i < 16; i++) xv[i] = xr[lane + 32 * i];

    float acc[20];
    #pragma unroll
    for (int g = 0; g < 4; g++) {
        float s = 0.f;
        #pragma unroll
        for (int i = 0; i < 16; i++) s += xv[i] * Wr[(lane + 32 * i) * 4 + g];
        acc[g] = s;
    }
    #pragma unroll
    for (int g = 0; g < 4; g++) {
        #pragma unroll
        for (int e = 0; e < 4; e++) {
            float s = 0.f;
            const float* wgp = Wg + (size_t)g * DDIM * EPG + e;
            #pragma unroll
            for (int i = 0; i < 16; i++) s += xv[i] * wgp[(lane + 32 * i) * 4];
            acc[4 + g * 4 + e] = s;
        }
    }
    #pragma unroll
    for (int o = 16; o; o >>= 1) {
        #pragma unroll
        for (int j = 0; j < 20; j++) acc[j] += __shfl_xor_sync(0xffffffffu, acc[j], o);
    }
    if (lane == 0) {
        float gl[4];
        #pragma unroll
        for (int g = 0; g < 4; g++) gl[g] = acc[g] + br[g];
        float wgrp[4];
        top2norm(gl, GTP_THR, wgrp);
        #pragma unroll
        for (int g = 0; g < 4; g++) {
            float el[4];
            #pragma unroll
            for (int e = 0; e < 4; e++) el[e] = acc[4 + g * 4 + e] + bg[g * 4 + e];
            float wexp[4];
            top2norm(el, TP_THR, wexp);
            #pragma unroll
            for (int e = 0; e < 4; e++) {
                d_tw[n * ENUM + g * 4 + e] = wgrp[g] * wexp[e] * SCALE_W;
                d_slot[n * ENUM + g * 4 + e] = -1;
            }
        }
    }
}

// ---------------- bucket build ----------------
__global__ __launch_bounds__(256) void build_buckets() {
    int e = blockIdx.x;
    int t = threadIdx.x;
    __shared__ int sc[256];
    int base = t * 8;
    float wv[8];
    int flags = 0, cnt = 0;
    #pragma unroll
    for (int j = 0; j < 8; j++) {
        float v = d_tw[(base + j) * ENUM + e];
        wv[j] = v;
        if (v > 0.f) { flags |= 1 << j; cnt++; }
    }
    sc[t] = cnt;
    __syncthreads();
    for (int off = 1; off < 256; off <<= 1) {
        int v = sc[t];
        int add = (t >= off) ? sc[t - off] : 0;
        __syncthreads();
        sc[t] = v + add;
        __syncthreads();
    }
    int pos = sc[t] - cnt;
    #pragma unroll
    for (int j = 0; j < 8; j++) {
        if ((flags >> j) & 1) {
            int n = base + j;
            d_bucket_tok[e * NTOK + pos] = n;
            d_bucket_w[e * NTOK + pos] = wv[j];
            d_slot[n * ENUM + e] = pos;
            pos++;
        }
    }
    if (t == 255) d_counts[e] = sc[255];
}

// no-op launch to position wmma_up in ncu's profiled slot (launch #4)
__global__ void nopk() {}

// =============================================================================
// wmma_up: block 128(M) x 128(N) for BOTH u=xW1 and v=xW3. K-chunk 32, 16 chunks.
// 8 warps (2m x 4n), warp tile 64x32 per output matrix: 8 frag loads / 16 MMAs.
// Double-buffered dynamic smem, register prefetch, one sync per chunk.
// Layout per buffer (halfs): Ah[128x40]@0  B1h[32x136]@5120  B3h[32x136]@9472
// =============================================================================
__global__ __launch_bounds__(256, 1) void wmma_up(
    const float* __restrict__ x, const float* __restrict__ W1,
    const float* __restrict__ W3)
{
    extern __shared__ __align__(16) __half SMU[];
    int e = blockIdx.z;
    int cnt = d_counts[e];
    if (cnt == 0) return;
    int cntp = (cnt + 127) & ~127;
    int m0 = blockIdx.y * 128;
    if (m0 >= cntp) return;
    int n0 = blockIdx.x * 128;
    int tid = threadIdx.x, lane = tid & 31, wid = tid >> 5;
    const int NK = DDIM / 32;

    int ar = tid >> 1, ap = (tid & 1) * 16;
    int gi = m0 + ar; if (gi > cnt - 1) gi = cnt - 1;
    const float* xrow = x + (size_t)d_bucket_tok[e * NTOK + gi] * DDIM;
    int kB = tid >> 3, cB = (tid & 7) * 16;
    const float* w1p = W1 + (size_t)e * DDIM * HDIM + (size_t)kB * HDIM + n0 + cB;
    const float* w3p = W3 + (size_t)e * DDIM * HDIM + (size_t)kB * HDIM + n0 + cB;

    float4 rA[4], rB1[4], rB3[4];
    auto ldreg = [&](int kc) {
        int k0 = kc * 32;
        #pragma unroll
        for (int q = 0; q < 4; q++) rA[q] = *(const float4*)(xrow + k0 + ap + q * 4);
        #pragma unroll
        for (int q = 0; q < 4; q++) {
            rB1[q] = *(const float4*)(w1p + (size_t)k0 * HDIM + q * 4);
            rB3[q] = *(const float4*)(w3p + (size_t)k0 * HDIM + q * 4);
        }
    };
    auto sts = [&](int b) {
        __half* Ah = SMU + b * UP_HALFS_PER_BUF;
        #pragma unroll
        for (int q = 0; q < 4; q++) cvthi4(rA[q], Ah + ar * 40 + ap + q * 4);
        __half* B1h = Ah + 5120;
        __half* B3h = Ah + 9472;
        #pragma unroll
        for (int q = 0; q < 4; q++) {
            cvthi4(rB1[q], B1h + kB * 136 + cB + q * 4);
            cvthi4(rB3[q], B3h + kB * 136 + cB + q * 4);
        }
    };

    int wm = wid & 1, wn = wid >> 1;
    wmma::fragment<wmma::accumulator, 16, 16, 16, float> u[4][2], v[4][2];
    #pragma unroll
    for (int i = 0; i < 4; i++)
        #pragma unroll
        for (int j = 0; j < 2; j++) {
            wmma::fill_fragment(u[i][j], 0.0f);
            wmma::fill_fragment(v[i][j], 0.0f);
        }

    ldreg(0);
    for (int kc = 0; kc < NK; kc++) {
        int b = kc & 1;
        sts(b);
        if (kc + 1 < NK) ldreg(kc + 1);
        __syncthreads();
        __half* Ah = SMU + b * UP_HALFS_PER_BUF;
        __half* B1h = Ah + 5120;
        __half* B3h = Ah + 9472;
        #pragma unroll
        for (int ks = 0; ks < 2; ks++) {
            wmma::fragment<wmma::matrix_a, 16, 16, 16, __half, wmma::row_major> fa[4];
            #pragma unroll
            for (int i = 0; i < 4; i++)
                wmma::load_matrix_sync(fa[i], Ah + (wm * 64 + 16 * i) * 40 + ks * 16, 40);
            wmma::fragment<wmma::matrix_b, 16, 16, 16, __half, wmma::row_major> f1[2], f3[2];
            #pragma unroll
            for (int j = 0; j < 2; j++) {
                int bo = ks * 16 * 136 + wn * 32 + 16 * j;
                wmma::load_matrix_sync(f1[j], B1h + bo, 136);
                wmma::load_matrix_sync(f3[j], B3h + bo, 136);
            }
            #pragma unroll
            for (int i = 0; i < 4; i++)
                #pragma unroll
                for (int j = 0; j < 2; j++) {
                    wmma::mma_sync(u[i][j], fa[i], f1[j], u[i][j]);
                    wmma::mma_sync(v[i][j], fa[i], f3[j], v[i][j]);
                }
        }
    }
    __syncthreads();

    // epilogue: h = silu(u)*v -> fp16
    float* epi = (float*)SMU + wid * 576;
    int r = lane >> 1, c0 = (lane & 1) * 8;
    #pragma unroll
    for (int i = 0; i < 4; i++)
        #pragma unroll
        for (int j = 0; j < 2; j++) {
            #pragma unroll
            for (int t = 0; t < u[i][j].num_elements; t++) {
                float uu = u[i][j].x[t];
                u[i][j].x[t] = uu / (1.f + __expf(-uu)) * v[i][j].x[t];
            }
            wmma::store_matrix_sync(epi, u[i][j], 36, wmma::mem_row_major);
            __syncwarp();
            int grow = m0 + wm * 64 + 16 * i + r;
            int gcol = n0 + wn * 32 + 16 * j + c0;
            __half2* op = (__half2*)(d_h16 + ((size_t)e * NTOK + grow) * HDIM + gcol);
            #pragma unroll
            for (int q = 0; q < 4; q++)
                op[q] = __floats2half2_rn(epi[r * 36 + c0 + 2 * q],
                                          epi[r * 36 + c0 + 2 * q + 1]);
            __syncwarp();
        }
}

// =============================================================================
// wmma_down: block 128(M) x 128(N). K-chunk 32, 64 chunks. 2 CTAs/SM.
// 8 warps (4m x 2n), warp tile 32x64, single live fb fragment to fit 128 regs.
// Static smem per buffer (halfs): Ah[128x40]@0  Bh[32x136]@5120  (9472)
// =============================================================================
__global__ __launch_bounds__(256, 2) void wmma_down(const float* __restrict__ W2)
{
    __shared__ __align__(16) __half SM[2][9472];   // 37888 B
    int e = blockIdx.z;
    int cnt = d_counts[e];
    if (cnt == 0) return;
    int cntp = (cnt + 127) & ~127;
    int m0 = blockIdx.y * 128;
    if (m0 >= cntp) return;
    int n0 = blockIdx.x * 128;
    int tid = threadIdx.x, lane = tid & 31, wid = tid >> 5;
    const int NK = HDIM / 32;

    int ar = tid >> 1, ap = (tid & 1) * 16;
    const __half* arow = d_h16 + ((size_t)e * NTOK + m0 + ar) * HDIM;
    int kB = tid >> 3, cB = (tid & 7) * 16;
    const float* w2p = W2 + (size_t)e * HDIM * DDIM + (size_t)kB * DDIM + n0 + cB;

    uint4 rA[2];
    float4 rB[4];
    auto ldreg = [&](int kc) {
        int k0 = kc * 32;
        rA[0] = *(const uint4*)(arow + k0 + ap);
        rA[1] = *(const uint4*)(arow + k0 + ap + 8);
        #pragma unroll
        for (int q = 0; q < 4; q++)
            rB[q] = *(const float4*)(w2p + (size_t)k0 * DDIM + q * 4);
    };
    auto sts = [&](int b) {
        __half* Ah = SM[b];
        *(uint4*)(Ah + ar * 40 + ap) = rA[0];
        *(uint4*)(Ah + ar * 40 + ap + 8) = rA[1];
        __half* Bh = SM[b] + 5120;
        #pragma unroll
        for (int q = 0; q < 4; q++)
            cvthi4(rB[q], Bh + kB * 136 + cB + q * 4);
    };

    int wm = wid & 3, wn = wid >> 2;
    wmma::fragment<wmma::accumulator, 16, 16, 16, float> c[2][4];
    #pragma unroll
    for (int i = 0; i < 2; i++)
        #pragma unroll
        for (int j = 0; j < 4; j++) wmma::fill_fragment(c[i][j], 0.0f);

    ldreg(0);
    for (int kc = 0; kc < NK; kc++) {
        int b = kc & 1;
        sts(b);
        if (kc + 1 < NK) ldreg(kc + 1);
        __syncthreads();
        __half* Ah = SM[b];
        __half* Bh = SM[b] + 5120;
        #pragma unroll
        for (int ks = 0; ks < 2; ks++) {
            wmma::fragment<wmma::matrix_a, 16, 16, 16, __half, wmma::row_major> fa[2];
            #pragma unroll
            for (int i = 0; i < 2; i++)
                wmma::load_matrix_sync(fa[i], Ah + (wm * 32 + 16 * i) * 40 + ks * 16, 40);
            #pragma unroll
            for (int j = 0; j < 4; j++) {
                wmma::fragment<wmma::matrix_b, 16, 16, 16, __half, wmma::row_major> fb;
                wmma::load_matrix_sync(fb, Bh + ks * 16 * 136 + wn * 64 + 16 * j, 136);
                wmma::mma_sync(c[0][j], fa[0], fb, c[0][j]);
                wmma::mma_sync(c[1][j], fa[1], fb, c[1][j]);
            }
        }
    }
    __syncthreads();

    float* epi = (float*)SM + wid * 576;
    int r = lane >> 1, c0 = (lane & 1) * 8;
    #pragma unroll
    for (int i = 0; i < 2; i++)
        #pragma unroll
        for (int j = 0; j < 4; j++) {
            wmma::store_matrix_sync(epi, c[i][j], 36, wmma::mem_row_major);
            __syncwarp();
            int grow = m0 + wm * 32 + 16 * i + r;
            float w = d_bucket_w[e * NTOK + grow];
            int gcol = n0 + wn * 64 + 16 * j + c0;
            float* op = d_partial + ((size_t)e * NTOK + grow) * DDIM + gcol;
            float4 o0 = { epi[r * 36 + c0] * w,     epi[r * 36 + c0 + 1] * w,
                          epi[r * 36 + c0 + 2] * w, epi[r * 36 + c0 + 3] * w };
            float4 o1 = { epi[r * 36 + c0 + 4] * w, epi[r * 36 + c0 + 5] * w,
                          epi[r * 36 + c0 + 6] * w, epi[r * 36 + c0 + 7] * w };
            *(float4*)op = o0;
            *(float4*)(op + 4) = o1;
            __syncwarp();
        }
}

// ---------------- gather ----------------
__global__ __launch_bounds__(128) void gather_out(float* __restrict__ out) {
    int n = blockIdx.x;
    int tid = threadIdx.x;
    float acc[4] = {0.f, 0.f, 0.f, 0.f};
    #pragma unroll
    for (int e = 0; e < ENUM; e++) {
        int s = d_slot[n * ENUM + e];
        if (s >= 0) {
            const float* pp = d_partial + ((size_t)e * NTOK + s) * DDIM;
            #pragma unroll
            for (int q = 0; q < 4; q++) acc[q] += pp[tid + q * 128];
        }
    }
    #pragma unroll
    for (int q = 0; q < 4; q++) out[(size_t)n * DDIM + tid + q * 128] = acc[q];
}

// ---------------- launch ----------------
extern "C" void kernel_launch(void* const* d_in, const int* in_sizes, int n_in,
                              void* d_out, int out_size)
{
    const float* x  = (const float*)d_in[0];
    const float* Wr = (const float*)d_in[1];
    const float* br = (const float*)d_in[2];
    const float* Wg = (const float*)d_in[3];
    const float* bg = (const float*)d_in[4];
    const float* W1 = (const float*)d_in[5];
    const float* W3 = (const float*)d_in[6];
    const float* W2 = (const float*)d_in[7];
    float* out = (float*)d_out;

    cudaFuncSetAttribute(wmma_up, cudaFuncAttributeMaxDynamicSharedMemorySize, UP_SMEM);

    routing_kernel<<<NTOK / 8, 256>>>(x, Wr, br, Wg, bg);                        // 1
    build_buckets<<<ENUM, 256>>>();                                               // 2
    nopk<<<1, 32>>>();                                                            // 3
    wmma_up<<<dim3(HDIM / 128, NTOK / 128, ENUM), 256, UP_SMEM>>>(x, W1, W3);    // 4 <- ncu
    wmma_down<<<dim3(DDIM / 128, NTOK / 128, ENUM), 256>>>(W2);                  // 5
    gather_out<<<NTOK, 128>>>(out);                                               // 6
}